// round 9
// baseline (speedup 1.0000x reference)
#include <cuda_runtime.h>

// RSI fused single pass, v9. out[c] = g/(g+l) over 13-wide window of
// positive/negative relative deltas (0 when no losses in window).
//
// v8 base + occupancy surgery: separate ov smem region removes the
// p-slot overwrite hazard, so neighbor LDS are staged inside the window
// loop (peak liveness down ~12 floats); __launch_bounds__(256,5) forces
// <=48 regs -> 5 blocks/SM (occ 62% vs 41%).

#define NROWS  2048
#define NCOLS  8192
#define TPB    256
#define ITEMS  16
#define WTILE  (32 * ITEMS)      // 512 outputs per warp
#define TILE   (8 * WTILE)       // 4096 outputs per block
#define MAXW   64
#define SLOT   20                // stride (conflict-free STS.128 / low-conflict reads)
#define PREG   (SLOT * 33)       // p region: 32 lanes + halo slot
#define OREG   (SLOT * 32)       // ov region: 32 lanes

__global__ __launch_bounds__(TPB, 5) void rsi_v9(
    const float* __restrict__ in,
    float* __restrict__ out,
    int out_cols)
{
    __shared__ __align__(16) float s_p[8 * PREG];
    __shared__ __align__(16) float s_o[8 * OREG];

    const int tid   = threadIdx.x;
    const int lane  = tid & 31;
    const int wrp   = tid >> 5;
    const int row   = blockIdx.y;
    const int wbase = blockIdx.x * TILE + wrp * WTILE;   // warp's first column
    const float* rin = in + (size_t)row * NCOLS;
    float* pw = s_p + wrp * PREG;
    float* ow = s_o + wrp * OREG;
    float* myp = pw + SLOT * lane;
    float* myo = ow + SLOT * lane;

    const bool edge = (wbase + WTILE) >= NCOLS;          // last warp of the row

    // ---- load own 16 inputs (wbase+512 <= 8192: always in-row) ----
    const int g0 = wbase + ITEMS * lane;
    const float4 xA = *(const float4*)(rin + g0);
    const float4 xB = *(const float4*)(rin + g0 + 4);
    const float4 xC = *(const float4*)(rin + g0 + 8);
    const float4 xD = *(const float4*)(rin + g0 + 12);

    // x[g0+16]: neighbor's first x via shuffle; lane 31 loads (guarded)
    float x16 = __shfl_down_sync(0xffffffffu, xA.x, 1);
    if (lane == 31)
        x16 = (!edge) ? rin[g0 + 16] : 0.0f;

    // halo x: lanes 0..12 load x[wbase+512+lane] (zero past row end)
    float xe = 0.0f;
    if (lane < 13) {
        const int ge = wbase + WTILE + lane;
        xe = (ge < NCOLS) ? rin[ge] : 0.0f;
    }
    const float xen = __shfl_down_sync(0xffffffffu, xe, 1);

    // ---- own 16 p-values ----
    const float xs[17] = {xA.x, xA.y, xA.z, xA.w, xB.x, xB.y, xB.z, xB.w,
                          xC.x, xC.y, xC.z, xC.w, xD.x, xD.y, xD.z, xD.w, x16};
    float p[ITEMS];
    #pragma unroll
    for (int c = 0; c < ITEMS; ++c) {
        const float prev = xs[c];
        p[c] = (prev != 0.0f) ? __fdividef(xs[c + 1] - prev, prev) : 0.0f;
    }

    // ---- publish p (stride-20, conflict-free STS.128) ----
    *(float4*)(myp)      = make_float4(p[0],  p[1],  p[2],  p[3]);
    *(float4*)(myp + 4)  = make_float4(p[4],  p[5],  p[6],  p[7]);
    *(float4*)(myp + 8)  = make_float4(p[8],  p[9],  p[10], p[11]);
    *(float4*)(myp + 12) = make_float4(p[12], p[13], p[14], p[15]);
    if (lane < 12) {                                     // halo p -> slot 32
        const float pe = (xe != 0.0f) ? __fdividef(xen - xe, xe) : 0.0f;
        pw[SLOT * 32 + lane] = pe;
    }
    __syncwarp();

    // ---- 16 sliding 13-windows; neighbor p staged in-loop.
    // L: prefix + snapshot (bitwise-exact l==0). S: sliding signed window.
    const float* nb = pw + SLOT * (lane + 1);            // lane 31 -> halo slot
    float n[12];
    float S = 0.0f, L = 0.0f;
    float ql[ITEMS], ov4[4];
    #pragma unroll
    for (int j = 0; j < ITEMS + 12; ++j) {
        if (j == 8)  { const float4 t = *(const float4*)(nb);
                       n[0] = t.x; n[1] = t.y; n[2]  = t.z; n[3]  = t.w; }
        if (j == 12) { const float4 t = *(const float4*)(nb + 4);
                       n[4] = t.x; n[5] = t.y; n[6]  = t.z; n[7]  = t.w; }
        if (j == 16) { const float4 t = *(const float4*)(nb + 8);
                       n[8] = t.x; n[9] = t.y; n[10] = t.z; n[11] = t.w; }

        const float vj = (j < ITEMS) ? p[j] : n[j - ITEMS];
        if (j < ITEMS) ql[j] = L;
        L += fmaxf(-vj, 0.0f);
        S += vj;
        if (j >= 13) S -= p[j - 13];                     // j-13 <= 14 < ITEMS
        if (j >= 12) {
            const int k = j - 12;
            const float l = L - ql[k];                   // exact over window
            const float t = S + l;                       // g = S + l
            ov4[k & 3] = (l != 0.0f) ? __fdividef(t, t + l) : 0.0f;
            if ((k & 3) == 3)
                *(float4*)(myo + (k - 3)) =
                    make_float4(ov4[0], ov4[1], ov4[2], ov4[3]);
        }
    }
    __syncwarp();

    // ---- coalesced scalar stores from transposed ov smem ----
    float* rout = out + (size_t)row * out_cols;
    if (!edge && wbase + WTILE <= out_cols) {
        #pragma unroll
        for (int m = 0; m < ITEMS; ++m) {
            const int o = lane + 32 * m;
            rout[wbase + o] = ow[SLOT * (o >> 4) + (o & 15)];
        }
    } else {
        #pragma unroll
        for (int m = 0; m < ITEMS; ++m) {
            const int o = lane + 32 * m;
            const int col = wbase + o;
            if (col < out_cols)
                rout[col] = ow[SLOT * (o >> 4) + (o & 15)];
        }
    }
}

// ---- Generic fallback for unexpected window sizes ----
__global__ __launch_bounds__(TPB) void rsi_generic(
    const float* __restrict__ in,
    float* __restrict__ out,
    int out_cols, int w)
{
    __shared__ float s_in[TPB + MAXW + 1];
    __shared__ float s_g [TPB + MAXW];
    __shared__ float s_l [TPB + MAXW];

    const int row  = blockIdx.y;
    const int base = blockIdx.x * TPB;
    const float* rin = in + (size_t)row * NCOLS;

    const int need_in = TPB + w + 1;
    for (int i = threadIdx.x; i < need_in; i += TPB) {
        const int col = base + i;
        s_in[i] = (col < NCOLS) ? rin[col] : 0.0f;
    }
    __syncthreads();

    const int need_p = TPB + w;
    for (int i = threadIdx.x; i < need_p; i += TPB) {
        const float prev = s_in[i];
        const float cur  = s_in[i + 1];
        const float p = (prev != 0.0f) ? (cur - prev) / prev : 0.0f;
        s_g[i] = fmaxf(p, 0.0f);
        s_l[i] = fmaxf(-p, 0.0f);
    }
    __syncthreads();

    const int c = base + threadIdx.x;
    if (c < out_cols) {
        float g = 0.0f, l = 0.0f;
        for (int j = 0; j < w; ++j) {
            g += s_g[threadIdx.x + j];
            l += s_l[threadIdx.x + j];
        }
        out[(size_t)row * out_cols + c] = (l != 0.0f) ? g / (g + l) : 0.0f;
    }
}

extern "C" void kernel_launch(void* const* d_in, const int* in_sizes, int n_in,
                              void* d_out, int out_size)
{
    const float* in  = (const float*)d_in[0];
    float*       out = (float*)d_out;

    const int out_cols = out_size / NROWS;   // NCOLS - (window_size - 1)
    int w = NCOLS - out_cols;

    if (w == 13) {
        dim3 grid((out_cols + TILE - 1) / TILE, NROWS);
        rsi_v9<<<grid, TPB>>>(in, out, out_cols);
    } else {
        if (w < 1)    w = 1;
        if (w > MAXW) w = MAXW;
        dim3 grid((out_cols + TPB - 1) / TPB, NROWS);
        rsi_generic<<<grid, TPB>>>(in, out, out_cols, w);
    }
}